// round 2
// baseline (speedup 1.0000x reference)
#include <cuda_runtime.h>
#include <math.h>

// Problem constants
#define NB     16
#define NTOK   1024
#define HEADS  8
#define DHEAD  64
#define INNER  512
#define QKVC   1536          // 3 * INNER
#define NNSQ   (NTOK * NTOK) // 1048576
#define ATT_SCALE 0.125f     // 64^-0.5

// ---------------------------------------------------------------------------
// Scratch (device globals; no runtime allocation allowed)
// ---------------------------------------------------------------------------
__device__ float g_qkv[(size_t)NB * NTOK * QKVC];   // [16384, 1536]  ~96 MB
__device__ float g_bias[(size_t)HEADS * NNSQ];      // [8, 1024, 1024] 32 MB (L2-resident)
__device__ float g_att[(size_t)NB * NTOK * INNER];  // [16384, 512]   32 MB

// ---------------------------------------------------------------------------
// Kernel 1: bias gather  bias[h][i][j] = rel_table[rel_index[i*N+j], h]
// ---------------------------------------------------------------------------
__global__ void bias_kernel(const int* __restrict__ rel_index,
                            const float* __restrict__ rel_table) {
    int t = blockIdx.x * blockDim.x + threadIdx.x;  // 0 .. NNSQ-1
    int idx = rel_index[t];
    #pragma unroll
    for (int h = 0; h < HEADS; h++) {
        g_bias[(size_t)h * NNSQ + t] = rel_table[idx * HEADS + h];
    }
}

// ---------------------------------------------------------------------------
// Kernel 2: fp32 tiled GEMM  C[M,N] = A[M,K] @ B[K,N] (+ bias[N])
// 128x128 tile, BK=8, 8x8 per thread, 256 threads. All dims divisible.
// ---------------------------------------------------------------------------
#define GBM 128
#define GBN 128
#define GBK 8

__global__ __launch_bounds__(256)
void gemm_kernel(const float* __restrict__ A,
                 const float* __restrict__ B,
                 float* __restrict__ C,
                 const float* __restrict__ bias,
                 int M, int Nn, int K, int hasBias) {
    __shared__ float As[GBK][GBM + 4];  // transposed A tile
    __shared__ float Bs[GBK][GBN + 4];

    const int tid = threadIdx.x;
    const int m0 = blockIdx.y * GBM;
    const int n0 = blockIdx.x * GBN;
    const int tx = tid & 15;       // 0..15
    const int ty = tid >> 4;       // 0..15
    const int tm = ty * 8;
    const int tn = tx * 8;

    float acc[8][8];
    #pragma unroll
    for (int i = 0; i < 8; i++)
        #pragma unroll
        for (int j = 0; j < 8; j++) acc[i][j] = 0.f;

    // load indices
    const int arow = tid >> 1;          // 0..127
    const int acol = (tid & 1) * 4;     // 0 or 4
    const int brow = tid >> 5;          // 0..7
    const int bcol = (tid & 31) * 4;    // 0..124

    const float* Aptr = A + (size_t)(m0 + arow) * K + acol;
    const float* Bptr = B + (size_t)brow * Nn + n0 + bcol;

    for (int k0 = 0; k0 < K; k0 += GBK) {
        float4 a4 = *(const float4*)(Aptr + k0);
        float4 b4 = *(const float4*)(Bptr + (size_t)k0 * Nn);
        As[acol + 0][arow] = a4.x;
        As[acol + 1][arow] = a4.y;
        As[acol + 2][arow] = a4.z;
        As[acol + 3][arow] = a4.w;
        *(float4*)&Bs[brow][bcol] = b4;
        __syncthreads();

        #pragma unroll
        for (int kk = 0; kk < GBK; kk++) {
            float a[8], b[8];
            *(float4*)(a)     = *(const float4*)&As[kk][tm];
            *(float4*)(a + 4) = *(const float4*)&As[kk][tm + 4];
            *(float4*)(b)     = *(const float4*)&Bs[kk][tn];
            *(float4*)(b + 4) = *(const float4*)&Bs[kk][tn + 4];
            #pragma unroll
            for (int i = 0; i < 8; i++)
                #pragma unroll
                for (int j = 0; j < 8; j++)
                    acc[i][j] += a[i] * b[j];
        }
        __syncthreads();
    }

    // epilogue
    #pragma unroll
    for (int i = 0; i < 8; i++) {
        float* crow = C + (size_t)(m0 + tm + i) * Nn + n0 + tn;
        #pragma unroll
        for (int j = 0; j < 8; j++) {
            float v = acc[i][j];
            if (hasBias) v += bias[n0 + tn + j];
            crow[j] = v;
        }
    }
}

// ---------------------------------------------------------------------------
// Kernel 3: fused attention with online softmax.
// grid = (16 query tiles, 8 heads, 16 batch); 256 threads.
// Each thread owns a 4x4 micro-tile (rows = queries, cols = keys or dims).
// Smem stride 65: lane row-stride 4*65=260 -> 260%32==4 -> worst 2-way conflict.
// ---------------------------------------------------------------------------
#define ASTR 65

__global__ __launch_bounds__(256)
void attn_kernel() {
    extern __shared__ float sm[];
    float* Qs = sm;                 // [64][ASTR]
    float* Ks = Qs + 64 * ASTR;
    float* Vs = Ks + 64 * ASTR;
    float* Ps = Vs + 64 * ASTR;

    const int qt = blockIdx.x;   // 0..15
    const int h  = blockIdx.y;   // 0..7
    const int b  = blockIdx.z;   // 0..15
    const int tid = threadIdx.x;
    const int tx = tid & 15;
    const int ty = tid >> 4;
    const int r0 = ty * 4;       // local query rows r0..r0+3
    const int c0 = tx * 4;       // local key/dim cols c0..c0+3
    const int q0 = qt * 64;

    // ---- load Q tile: rows [q0, q0+64), cols [h*64, h*64+64) of q section ----
    {
        for (int i = tid; i < 64 * 16; i += 256) {
            int r  = i >> 4;
            int d4 = (i & 15) * 4;
            float4 v = *(const float4*)(g_qkv +
                (size_t)(b * NTOK + q0 + r) * QKVC + h * DHEAD + d4);
            float* dst = &Qs[r * ASTR + d4];
            dst[0] = v.x; dst[1] = v.y; dst[2] = v.z; dst[3] = v.w;
        }
    }

    float m[4], l[4], o[4][4];
    #pragma unroll
    for (int i = 0; i < 4; i++) {
        m[i] = -INFINITY; l[i] = 0.f;
        #pragma unroll
        for (int j = 0; j < 4; j++) o[i][j] = 0.f;
    }

    const float* Qb = &Qs[r0 * ASTR];
    const float* Kb = &Ks[c0 * ASTR];

    for (int kt = 0; kt < 16; kt++) {
        const int k0 = kt * 64;
        __syncthreads();  // prev-iter PV done before overwriting K/V (also covers Q load)

        // ---- load K and V tiles ----
        for (int i = tid; i < 64 * 16; i += 256) {
            int r  = i >> 4;
            int d4 = (i & 15) * 4;
            size_t row = (size_t)(b * NTOK + k0 + r) * QKVC + h * DHEAD + d4;
            float4 kv = *(const float4*)(g_qkv + row + INNER);       // k section
            float4 vv = *(const float4*)(g_qkv + row + 2 * INNER);   // v section
            float* kd = &Ks[r * ASTR + d4];
            kd[0] = kv.x; kd[1] = kv.y; kd[2] = kv.z; kd[3] = kv.w;
            float* vd = &Vs[r * ASTR + d4];
            vd[0] = vv.x; vd[1] = vv.y; vd[2] = vv.z; vd[3] = vv.w;
        }
        __syncthreads();

        // ---- S = Q @ K^T (4x4 per thread) ----
        float s[4][4];
        #pragma unroll
        for (int i = 0; i < 4; i++)
            #pragma unroll
            for (int j = 0; j < 4; j++) s[i][j] = 0.f;

        #pragma unroll 8
        for (int d = 0; d < 64; d++) {
            float qf[4], kf[4];
            #pragma unroll
            for (int i = 0; i < 4; i++) qf[i] = Qb[i * ASTR + d];
            #pragma unroll
            for (int j = 0; j < 4; j++) kf[j] = Kb[j * ASTR + d];
            #pragma unroll
            for (int i = 0; i < 4; i++)
                #pragma unroll
                for (int j = 0; j < 4; j++)
                    s[i][j] += qf[i] * kf[j];
        }

        // ---- scale + bias + online softmax update ----
        #pragma unroll
        for (int i = 0; i < 4; i++) {
            const float* bp = g_bias + ((size_t)h << 20)
                            + (size_t)(q0 + r0 + i) * NTOK + k0 + c0;
            #pragma unroll
            for (int j = 0; j < 4; j++)
                s[i][j] = s[i][j] * ATT_SCALE + bp[j];

            float tmax = fmaxf(fmaxf(s[i][0], s[i][1]), fmaxf(s[i][2], s[i][3]));
            // reduce across the 16 lanes sharing this row (lanes contiguous in lane-id)
            #pragma unroll
            for (int off = 1; off < 16; off <<= 1)
                tmax = fmaxf(tmax, __shfl_xor_sync(0xffffffffu, tmax, off));

            float mnew = fmaxf(m[i], tmax);
            float corr = __expf(m[i] - mnew);   // 0 on first tile (m=-inf)
            float p[4], rs = 0.f;
            #pragma unroll
            for (int j = 0; j < 4; j++) {
                p[j] = __expf(s[i][j] - mnew);
                rs += p[j];
            }
            #pragma unroll
            for (int off = 1; off < 16; off <<= 1)
                rs += __shfl_xor_sync(0xffffffffu, rs, off);

            l[i] = l[i] * corr + rs;
            m[i] = mnew;
            #pragma unroll
            for (int j = 0; j < 4; j++) o[i][j] *= corr;

            float* pr = &Ps[(r0 + i) * ASTR + c0];
            #pragma unroll
            for (int j = 0; j < 4; j++) pr[j] = p[j];
        }
        __syncthreads();  // Ps visible to all before PV

        // ---- O += P @ V ----
        #pragma unroll 8
        for (int j = 0; j < 64; j++) {
            float pf[4], vf[4];
            #pragma unroll
            for (int i = 0; i < 4; i++) pf[i] = Ps[(r0 + i) * ASTR + j];
            #pragma unroll
            for (int d = 0; d < 4; d++) vf[d] = Vs[j * ASTR + c0 + d];
            #pragma unroll
            for (int i = 0; i < 4; i++)
                #pragma unroll
                for (int d = 0; d < 4; d++)
                    o[i][d] += pf[i] * vf[d];
        }
    }

    // ---- epilogue: normalize and write [b, n, h*64+d] ----
    #pragma unroll
    for (int i = 0; i < 4; i++) {
        float inv = 1.0f / l[i];
        float* orow = g_att + (size_t)(b * NTOK + q0 + r0 + i) * INNER
                    + h * DHEAD + c0;
        #pragma unroll
        for (int d = 0; d < 4; d++) orow[d] = o[i][d] * inv;
    }
}

// ---------------------------------------------------------------------------
// Launch
// ---------------------------------------------------------------------------
extern "C" void kernel_launch(void* const* d_in, const int* in_sizes, int n_in,
                              void* d_out, int out_size) {
    const float* x         = (const float*)d_in[0];  // [16,1024,512]
    const float* Wqkv      = (const float*)d_in[1];  // [512,1536]
    const float* rel_table = (const float*)d_in[2];  // [3969,8]
    const float* Wout      = (const float*)d_in[3];  // [512,512]
    const float* bout      = (const float*)d_in[4];  // [512]
    const int*   rel_index = (const int*)d_in[5];    // [1048576]
    float*       out       = (float*)d_out;          // [16,1024,512]

    float *qkv_p = nullptr, *att_p = nullptr;
    cudaGetSymbolAddress((void**)&qkv_p, g_qkv);
    cudaGetSymbolAddress((void**)&att_p, g_att);

    // 1) bias gather
    bias_kernel<<<NNSQ / 256, 256>>>(rel_index, rel_table);

    // 2) QKV GEMM: [16384,512] @ [512,1536]
    {
        dim3 g(QKVC / GBN, (NB * NTOK) / GBM);
        gemm_kernel<<<g, 256>>>(x, Wqkv, qkv_p, nullptr,
                                NB * NTOK, QKVC, INNER, 0);
    }

    // 3) fused attention
    {
        const int smem = 4 * 64 * ASTR * (int)sizeof(float);  // 66560 B
        cudaFuncSetAttribute(attn_kernel,
                             cudaFuncAttributeMaxDynamicSharedMemorySize, smem);
        dim3 g(NTOK / 64, HEADS, NB);
        attn_kernel<<<g, 256, smem>>>();
    }

    // 4) output projection: [16384,512] @ [512,512] + b_out
    {
        dim3 g(INNER / GBN, (NB * NTOK) / GBM);
        gemm_kernel<<<g, 256>>>(att_p, Wout, out, bout,
                                NB * NTOK, INNER, INNER, 1);
    }
}

// round 7
// speedup vs baseline: 4.3900x; 4.3900x over previous
#include <cuda_runtime.h>
#include <cuda_fp16.h>
#include <mma.h>
#include <math.h>
#include <stdint.h>

using namespace nvcuda;

// ---------------- problem constants ----------------
#define NB     16
#define NTOK   1024
#define HEADS  8
#define DHEAD  64
#define INNER  512
#define QKVC   1536
#define NNSQ   (NTOK * NTOK)
#define MTOT   (NB * NTOK)          // 16384
#define ATT_SCALE 0.125f

// ---------------- device scratch ----------------
__device__ __half g_xh   [(size_t)MTOT * INNER];    // x fp16
__device__ __half g_wqkvh[(size_t)INNER * QKVC];    // Wqkv fp16 [K,N] row-major
__device__ __half g_wouth[(size_t)INNER * INNER];   // Wout fp16 [K,N]
__device__ __half g_qkvh [(size_t)MTOT * QKVC];     // qkv fp16
__device__ __half g_biash[(size_t)HEADS * NNSQ];    // bias fp16 (L2-resident)
__device__ __half g_atth [(size_t)MTOT * INNER];    // attention out fp16

// ---------------- prep kernels ----------------
__global__ void convert_x_kernel(const float* __restrict__ x) {
    size_t i = (size_t)blockIdx.x * 256 + threadIdx.x;
    float2 v = ((const float2*)x)[i];
    ((__half2*)g_xh)[i] = __floats2half2_rn(v.x, v.y);
}
__global__ void convert_w_kernel(const float* __restrict__ W, __half* __restrict__ Wh,
                                 int total) {
    int i = blockIdx.x * 256 + threadIdx.x;
    if (i < total) Wh[i] = __float2half(W[i]);
}
__global__ void bias_kernel(const int* __restrict__ ri, const float* __restrict__ rt) {
    int t = blockIdx.x * 256 + threadIdx.x;
    int idx = ri[t];
    #pragma unroll
    for (int h = 0; h < HEADS; h++)
        g_biash[(size_t)h * NNSQ + t] = __float2half(rt[idx * HEADS + h]);
}

// ---------------- wmma GEMM: C[M,N] = A[M,K]h @ B[K,N]h ----------------
// CTA tile 128x128, BK=64, 8 warps (4 x 2), warp tile 32x64.
#define ALD 80     // As row stride (halfs)
#define BLD 136    // Bs row stride (halfs)

__global__ __launch_bounds__(256)
void gemm_wmma_kernel(const __half* __restrict__ A, const __half* __restrict__ B,
                      __half* __restrict__ Ch, float* __restrict__ Cf,
                      const float* __restrict__ bias, int Nn, int K, int outHalf) {
    __shared__ __half As[128 * ALD];
    __shared__ __half Bs[64 * BLD];
    __shared__ float  buf[8][16 * 20];

    const int tid = threadIdx.x, wid = tid >> 5, lane = tid & 31;
    const int wm = wid & 3, wn = wid >> 2;
    const int m0 = blockIdx.y * 128, n0 = blockIdx.x * 128;

    wmma::fragment<wmma::accumulator, 16, 16, 16, float> c[2][4];
    #pragma unroll
    for (int i = 0; i < 2; i++)
        #pragma unroll
        for (int j = 0; j < 4; j++) wmma::fill_fragment(c[i][j], 0.0f);

    for (int kb = 0; kb < K; kb += 64) {
        __syncthreads();
        // load A tile 128x64
        #pragma unroll
        for (int i = tid; i < 1024; i += 256) {
            int r = i >> 3, cc = (i & 7) * 8;
            float4 v = *(const float4*)(A + (size_t)(m0 + r) * K + kb + cc);
            *(float4*)&As[r * ALD + cc] = v;
        }
        // load B tile 64x128
        #pragma unroll
        for (int i = tid; i < 1024; i += 256) {
            int r = i >> 4, cc = (i & 15) * 8;
            float4 v = *(const float4*)(B + (size_t)(kb + r) * Nn + n0 + cc);
            *(float4*)&Bs[r * BLD + cc] = v;
        }
        __syncthreads();

        #pragma unroll
        for (int kk = 0; kk < 4; kk++) {
            wmma::fragment<wmma::matrix_a, 16, 16, 16, __half, wmma::row_major> a[2];
            wmma::fragment<wmma::matrix_b, 16, 16, 16, __half, wmma::row_major> bfr[4];
            #pragma unroll
            for (int i = 0; i < 2; i++)
                wmma::load_matrix_sync(a[i], &As[(wm * 32 + i * 16) * ALD + kk * 16], ALD);
            #pragma unroll
            for (int j = 0; j < 4; j++)
                wmma::load_matrix_sync(bfr[j], &Bs[(kk * 16) * BLD + wn * 64 + j * 16], BLD);
            #pragma unroll
            for (int i = 0; i < 2; i++)
                #pragma unroll
                for (int j = 0; j < 4; j++)
                    wmma::mma_sync(c[i][j], a[i], bfr[j], c[i][j]);
        }
    }

    // epilogue via per-warp smem staging
    #pragma unroll
    for (int i = 0; i < 2; i++) {
        #pragma unroll
        for (int j = 0; j < 4; j++) {
            wmma::store_matrix_sync(&buf[wid][0], c[i][j], 20, wmma::mem_row_major);
            __syncwarp();
            int r   = lane >> 1;
            int cl  = (lane & 1) * 8;
            int row = m0 + wm * 32 + i * 16 + r;
            int col = n0 + wn * 64 + j * 16 + cl;
            const float* src = &buf[wid][r * 20 + cl];
            if (outHalf) {
                __half2 h2[4];
                #pragma unroll
                for (int q = 0; q < 4; q++)
                    h2[q] = __floats2half2_rn(src[2 * q], src[2 * q + 1]);
                *(float4*)(Ch + (size_t)row * Nn + col) = *(float4*)h2;
            } else {
                float v[8];
                #pragma unroll
                for (int q = 0; q < 8; q++) v[q] = src[q] + bias[col + q];
                float* dst = Cf + (size_t)row * Nn + col;
                *(float4*)dst = *(float4*)v;
                *(float4*)(dst + 4) = *(float4*)(v + 4);
            }
            __syncwarp();
        }
    }
}

// ---------------- mma.sync flash attention (no max subtraction) ----------------
// grid (16 qtiles, 8 heads, 16 batch), 128 threads (4 warps).
// Warp wq owns query rows [wq*16, wq*16+16). KV tile = 64 keys.
#define KLD 88   // Ks/Vt row stride in halfs (conflict-free for half2 frag loads)

__device__ __forceinline__ void mma16816(float* d, const uint32_t* a, const uint32_t* b) {
    asm volatile(
        "mma.sync.aligned.m16n8k16.row.col.f32.f16.f16.f32 "
        "{%0,%1,%2,%3}, {%4,%5,%6,%7}, {%8,%9}, {%0,%1,%2,%3};"
        : "+f"(d[0]), "+f"(d[1]), "+f"(d[2]), "+f"(d[3])
        : "r"(a[0]), "r"(a[1]), "r"(a[2]), "r"(a[3]), "r"(b[0]), "r"(b[1]));
}

__global__ __launch_bounds__(128)
void attn_mma_kernel() {
    __shared__ __half Ks[64 * KLD];
    __shared__ __half Vt[64 * KLD];

    const int qt = blockIdx.x, h = blockIdx.y, b = blockIdx.z;
    const int q0 = qt * 64;
    const int tid = threadIdx.x, wq = tid >> 5, lane = tid & 31;
    const int g = lane >> 2, tig = lane & 3;

    // ---- Q fragments (A operand), loaded once from gmem ----
    uint32_t aQ[4][4];
    {
        const __half* q0p = g_qkvh + (size_t)(b * NTOK + q0 + wq * 16 + g) * QKVC + h * DHEAD;
        const __half* q8p = q0p + (size_t)8 * QKVC;
        #pragma unroll
        for (int kc = 0; kc < 4; kc++) {
            aQ[kc][0] = *(const uint32_t*)(q0p + kc * 16 + tig * 2);
            aQ[kc][1] = *(const uint32_t*)(q8p + kc * 16 + tig * 2);
            aQ[kc][2] = *(const uint32_t*)(q0p + kc * 16 + 8 + tig * 2);
            aQ[kc][3] = *(const uint32_t*)(q8p + kc * 16 + 8 + tig * 2);
        }
    }

    float o[8][4];
    #pragma unroll
    for (int i = 0; i < 8; i++)
        #pragma unroll
        for (int j = 0; j < 4; j++) o[i][j] = 0.f;
    float l0 = 0.f, l1 = 0.f;

    const __half* bias0 = g_biash + ((size_t)h << 20)
                        + (size_t)(q0 + wq * 16 + g) * NTOK;
    const __half* bias8 = bias0 + (size_t)8 * NTOK;

    for (int kt = 0; kt < 16; kt++) {
        const int k0 = kt * 64;
        __syncthreads();   // previous iter done with Ks/Vt
        // ---- load K tile [64 keys][64 d] ----
        #pragma unroll
        for (int i = tid; i < 512; i += 128) {
            int r = i >> 3, cc = (i & 7) * 8;
            float4 v = *(const float4*)(g_qkvh +
                (size_t)(b * NTOK + k0 + r) * QKVC + INNER + h * DHEAD + cc);
            *(float4*)&Ks[r * KLD + cc] = v;
        }
        // ---- load V tile transposed: Vt[d][key] ----
        #pragma unroll
        for (int i = tid; i < 512; i += 128) {
            int r = i >> 3, cc = (i & 7) * 8;
            float4 v = *(const float4*)(g_qkvh +
                (size_t)(b * NTOK + k0 + r) * QKVC + 2 * INNER + h * DHEAD + cc);
            const __half* hv = (const __half*)&v;
            #pragma unroll
            for (int j = 0; j < 8; j++)
                Vt[(cc + j) * KLD + r] = hv[j];
        }
        __syncthreads();

        // ---- S = Q @ K^T : c frags over 8 n-tiles ----
        float cS[8][4];
        #pragma unroll
        for (int nt = 0; nt < 8; nt++)
            #pragma unroll
            for (int j = 0; j < 4; j++) cS[nt][j] = 0.f;

        #pragma unroll
        for (int kc = 0; kc < 4; kc++) {
            uint32_t bK[8][2];
            #pragma unroll
            for (int nt = 0; nt < 8; nt++) {
                const __half* kp = &Ks[(g + nt * 8) * KLD + tig * 2 + kc * 16];
                bK[nt][0] = *(const uint32_t*)kp;
                bK[nt][1] = *(const uint32_t*)(kp + 8);
            }
            #pragma unroll
            for (int nt = 0; nt < 8; nt++)
                mma16816(cS[nt], aQ[kc], bK[nt]);
        }

        // ---- scale + bias + exp, pack P A-fragments ----
        uint32_t pa[4][4];
        #pragma unroll
        for (int nt = 0; nt < 8; nt++) {
            __half2 b0 = *(const __half2*)(bias0 + k0 + nt * 8 + tig * 2);
            __half2 b8 = *(const __half2*)(bias8 + k0 + nt * 8 + tig * 2);
            float e0 = __expf(cS[nt][0] * ATT_SCALE + __low2float(b0));
            float e1 = __expf(cS[nt][1] * ATT_SCALE + __high2float(b0));
            float e2 = __expf(cS[nt][2] * ATT_SCALE + __low2float(b8));
            float e3 = __expf(cS[nt][3] * ATT_SCALE + __high2float(b8));
            l0 += e0 + e1;
            l1 += e2 + e3;
            __half2 p01 = __floats2half2_rn(e0, e1);
            __half2 p23 = __floats2half2_rn(e2, e3);
            pa[nt >> 1][(nt & 1) * 2 + 0] = *(uint32_t*)&p01;
            pa[nt >> 1][(nt & 1) * 2 + 1] = *(uint32_t*)&p23;
        }

        // ---- O += P @ V ----
        #pragma unroll
        for (int kc = 0; kc < 4; kc++) {
            uint32_t bV[8][2];
            #pragma unroll
            for (int dt = 0; dt < 8; dt++) {
                const __half* vp = &Vt[(g + dt * 8) * KLD + tig * 2 + kc * 16];
                bV[dt][0] = *(const uint32_t*)vp;
                bV[dt][1] = *(const uint32_t*)(vp + 8);
            }
            #pragma unroll
            for (int dt = 0; dt < 8; dt++)
                mma16816(o[dt], pa[kc], bV[dt]);
        }
    }

    // ---- row sums across the 4 lanes of each group ----
    l0 += __shfl_xor_sync(0xffffffffu, l0, 1);
    l0 += __shfl_xor_sync(0xffffffffu, l0, 2);
    l1 += __shfl_xor_sync(0xffffffffu, l1, 1);
    l1 += __shfl_xor_sync(0xffffffffu, l1, 2);
    const float inv0 = 1.0f / l0, inv1 = 1.0f / l1;

    // ---- write O (fp16) ----
    __half* out0 = g_atth + (size_t)(b * NTOK + q0 + wq * 16 + g) * INNER + h * DHEAD;
    __half* out8 = out0 + (size_t)8 * INNER;
    #pragma unroll
    for (int dt = 0; dt < 8; dt++) {
        __half2 r0 = __floats2half2_rn(o[dt][0] * inv0, o[dt][1] * inv0);
        __half2 r8 = __floats2half2_rn(o[dt][2] * inv1, o[dt][3] * inv1);
        *(__half2*)(out0 + dt * 8 + tig * 2) = r0;
        *(__half2*)(out8 + dt * 8 + tig * 2) = r8;
    }
}

// ---------------- launch ----------------
extern "C" void kernel_launch(void* const* d_in, const int* in_sizes, int n_in,
                              void* d_out, int out_size) {
    const float* x         = (const float*)d_in[0];
    const float* Wqkv      = (const float*)d_in[1];
    const float* rel_table = (const float*)d_in[2];
    const float* Wout      = (const float*)d_in[3];
    const float* bout      = (const float*)d_in[4];
    const int*   rel_index = (const int*)d_in[5];
    float*       out       = (float*)d_out;

    __half *xh, *wqkvh, *wouth, *qkvh, *atth;
    cudaGetSymbolAddress((void**)&xh,    g_xh);
    cudaGetSymbolAddress((void**)&wqkvh, g_wqkvh);
    cudaGetSymbolAddress((void**)&wouth, g_wouth);
    cudaGetSymbolAddress((void**)&qkvh,  g_qkvh);
    cudaGetSymbolAddress((void**)&atth,  g_atth);

    // prep
    convert_x_kernel<<<(MTOT * INNER / 2) / 256, 256>>>(x);
    convert_w_kernel<<<(INNER * QKVC + 255) / 256, 256>>>(Wqkv, wqkvh, INNER * QKVC);
    convert_w_kernel<<<(INNER * INNER + 255) / 256, 256>>>(Wout, wouth, INNER * INNER);
    bias_kernel<<<NNSQ / 256, 256>>>(rel_index, rel_table);

    // QKV GEMM: [16384,512] @ [512,1536] -> fp16
    {
        dim3 g(QKVC / 128, MTOT / 128);
        gemm_wmma_kernel<<<g, 256>>>(xh, wqkvh, qkvh, nullptr, nullptr,
                                     QKVC, INNER, 1);
    }
    // attention
    {
        dim3 g(NTOK / 64, HEADS, NB);
        attn_mma_kernel<<<g, 128>>>();
    }
    // out projection: [16384,512] @ [512,512] + bias -> fp32
    {
        dim3 g(INNER / 128, MTOT / 128);
        gemm_wmma_kernel<<<g, 256>>>(atth, wouth, nullptr, out, bout,
                                     INNER, INNER, 0);
    }
}